// round 14
// baseline (speedup 1.0000x reference)
#include <cuda_runtime.h>
#include <cuda_bf16.h>
#include <math.h>
#include <stdint.h>

#define S_LEN 2048
#define HIDDIM 2048
#define NH 16
#define NKV 4
#define HD 128
#define NQD (NH*HD)    // 2048
#define NKD (NKV*HD)   // 512
#define WIN 1024
#define KDIM 2048

// ---------------- scratch ---------------------------------------------------
__device__ float g_Q[S_LEN * NQD];
__device__ float g_K[S_LEN * NKD];

__device__ __nv_bfloat16 g_xh[S_LEN * HIDDIM], g_xl[S_LEN * HIDDIM];
__device__ __nv_bfloat16 g_wqh[NQD * HIDDIM],  g_wql[NQD * HIDDIM];
__device__ __nv_bfloat16 g_wkh[NKD * HIDDIM],  g_wkl[NKD * HIDDIM];
__device__ __nv_bfloat16 g_wvh[NKD * HIDDIM],  g_wvl[NKD * HIDDIM];
__device__ __nv_bfloat16 g_woh[HIDDIM * NQD],  g_wol[HIDDIM * NQD];
__device__ __nv_bfloat16 g_ah[S_LEN * NQD],    g_al[S_LEN * NQD];

__device__ __nv_bfloat16 g_Qh[S_LEN * NQD], g_Ql[S_LEN * NQD];
__device__ __nv_bfloat16 g_Kh[S_LEN * NKD], g_Kl[S_LEN * NKD];
__device__ __nv_bfloat16 g_Vh[S_LEN * NKD], g_Vl[S_LEN * NKD];

// ---------------- helpers ---------------------------------------------------
__device__ __forceinline__ uint32_t smem_u32(const void* p) {
    uint32_t a;
    asm("{ .reg .u64 t; cvta.to.shared.u64 t, %1; cvt.u32.u64 %0, t; }"
        : "=r"(a) : "l"(p));
    return a;
}

__device__ __forceinline__ void cp16(uint32_t dst, const void* src) {
    asm volatile("cp.async.cg.shared.global [%0], [%1], 16;" :: "r"(dst), "l"(src));
}

__device__ __forceinline__ void mma16816(float* c, const uint32_t* a,
                                         uint32_t b0, uint32_t b1) {
    asm volatile(
        "mma.sync.aligned.m16n8k16.row.col.f32.bf16.bf16.f32 "
        "{%0,%1,%2,%3}, {%4,%5,%6,%7}, {%8,%9}, {%0,%1,%2,%3};"
        : "+f"(c[0]), "+f"(c[1]), "+f"(c[2]), "+f"(c[3])
        : "r"(a[0]), "r"(a[1]), "r"(a[2]), "r"(a[3]), "r"(b0), "r"(b1));
}

__device__ __forceinline__ void ldsm4(uint32_t* r, uint32_t addr) {
    asm volatile("ldmatrix.sync.aligned.m8n8.x4.shared.b16 {%0,%1,%2,%3}, [%4];"
                 : "=r"(r[0]), "=r"(r[1]), "=r"(r[2]), "=r"(r[3]) : "r"(addr));
}

__device__ __forceinline__ void ldsm4t(uint32_t& r0, uint32_t& r1,
                                       uint32_t& r2, uint32_t& r3, uint32_t addr) {
    asm volatile("ldmatrix.sync.aligned.m8n8.x4.trans.shared.b16 {%0,%1,%2,%3}, [%4];"
                 : "=r"(r0), "=r"(r1), "=r"(r2), "=r"(r3) : "r"(addr));
}

__device__ __forceinline__ uint32_t pack_bf2(float x, float y) {
    __nv_bfloat16 hx = __float2bfloat16(x), hy = __float2bfloat16(y);
    return (uint32_t)__bfloat16_as_ushort(hx) |
           ((uint32_t)__bfloat16_as_ushort(hy) << 16);
}

// ---------------------------------------------------------------------------
// fused split: x, wq, wk, wv, wo -> bf16 hi/lo. 4 float4 per thread (MLP=4).
// ---------------------------------------------------------------------------
__device__ __forceinline__ void split_store(float4 v,
                                            __nv_bfloat16* __restrict__ hi,
                                            __nv_bfloat16* __restrict__ lo, int i) {
    __nv_bfloat16 h0 = __float2bfloat16(v.x);
    __nv_bfloat16 h1 = __float2bfloat16(v.y);
    __nv_bfloat16 h2 = __float2bfloat16(v.z);
    __nv_bfloat16 h3 = __float2bfloat16(v.w);
    __nv_bfloat16 l0 = __float2bfloat16(v.x - __bfloat162float(h0));
    __nv_bfloat16 l1 = __float2bfloat16(v.y - __bfloat162float(h1));
    __nv_bfloat16 l2 = __float2bfloat16(v.z - __bfloat162float(h2));
    __nv_bfloat16 l3 = __float2bfloat16(v.w - __bfloat162float(h3));
    uint2 hv, lv;
    hv.x = (uint32_t)__bfloat16_as_ushort(h0) | ((uint32_t)__bfloat16_as_ushort(h1) << 16);
    hv.y = (uint32_t)__bfloat16_as_ushort(h2) | ((uint32_t)__bfloat16_as_ushort(h3) << 16);
    lv.x = (uint32_t)__bfloat16_as_ushort(l0) | ((uint32_t)__bfloat16_as_ushort(l1) << 16);
    lv.y = (uint32_t)__bfloat16_as_ushort(l2) | ((uint32_t)__bfloat16_as_ushort(l3) << 16);
    ((uint2*)hi)[i] = hv;
    ((uint2*)lo)[i] = lv;
}

#define XQ4  262144
#define WQQ4 262144
#define WKQ4 65536
#define WVQ4 65536
#define WOQ4 262144
#define SPLIT_THREADS (XQ4 + WQQ4 + WKQ4 + WVQ4 + WOQ4)

__global__ void splitAll_kernel(const float* __restrict__ x,
                                const float* __restrict__ wq,
                                const float* __restrict__ wk,
                                const float* __restrict__ wv,
                                const float* __restrict__ wo,
                                __nv_bfloat16* xh, __nv_bfloat16* xl,
                                __nv_bfloat16* wqh, __nv_bfloat16* wql,
                                __nv_bfloat16* wkh, __nv_bfloat16* wkl,
                                __nv_bfloat16* wvh, __nv_bfloat16* wvl,
                                __nv_bfloat16* woh, __nv_bfloat16* wol) {
    int i = blockIdx.x * blockDim.x + threadIdx.x;
    const float* in; __nv_bfloat16 *hi, *lo; int base, qtr;
    if (i < XQ4)                       { in = x;  hi = xh;  lo = xl;  base = i;                      qtr = XQ4;  }
    else if (i < XQ4+WQQ4)             { in = wq; hi = wqh; lo = wql; base = i - XQ4;                qtr = WQQ4; }
    else if (i < XQ4+WQQ4+WKQ4)        { in = wk; hi = wkh; lo = wkl; base = i - XQ4-WQQ4;           qtr = WKQ4; }
    else if (i < XQ4+WQQ4+WKQ4+WVQ4)   { in = wv; hi = wvh; lo = wvl; base = i - XQ4-WQQ4-WKQ4;      qtr = WVQ4; }
    else                               { in = wo; hi = woh; lo = wol; base = i - XQ4-WQQ4-WKQ4-WVQ4; qtr = WOQ4; }
    const float4* in4 = (const float4*)in;
    float4 v0 = in4[base];
    float4 v1 = in4[base + qtr];
    float4 v2 = in4[base + 2 * qtr];
    float4 v3 = in4[base + 3 * qtr];
    split_store(v0, hi, lo, base);
    split_store(v1, hi, lo, base + qtr);
    split_store(v2, hi, lo, base + 2 * qtr);
    split_store(v3, hi, lo, base + 3 * qtr);
}

// ---------------------------------------------------------------------------
// HMMA GEMM core (proven R11 config, untouched).
// ---------------------------------------------------------------------------
#define BM 128
#define BN 128
#define BKG 32
#define ASTRIDE 40
#define TILE_B (128 * ASTRIDE * 2)
#define STAGE_B (4 * TILE_B)
#define GEMM_SMEM (2 * STAGE_B)          // 81920
#define NST (KDIM / BKG)

__device__ __forceinline__ void gemm_body(const __nv_bfloat16* __restrict__ Ahg,
                                          const __nv_bfloat16* __restrict__ Alg,
                                          const __nv_bfloat16* __restrict__ Bhg,
                                          const __nv_bfloat16* __restrict__ Blg,
                                          float* __restrict__ C,
                                          __nv_bfloat16* __restrict__ Ch,
                                          __nv_bfloat16* __restrict__ Cl,
                                          int N, int mBase, int nBase, char* smg) {
    const int t = threadIdx.x;
    const int wid = t >> 5, lane = t & 31;
    const int g = lane >> 2, tq = lane & 3;
    const int wm = wid & 3, wn = wid >> 2;

    float acc[2][8][4] = {};

    const int chunk = t & 3;
    const int row0 = t >> 2;

    const int sub16 = lane & 15;
    const int hi8 = (lane >> 4) << 3;
    const int q2 = lane >> 3, sub8 = lane & 7;
    const int loffA0 = ((wm * 32 + sub16) * ASTRIDE + hi8) * 2;
    const int loffA1 = ((wm * 32 + 16 + sub16) * ASTRIDE + hi8) * 2;
    const int loffB  = ((wn * 64 + ((q2 >> 1) << 3) + sub8) * ASTRIDE + ((q2 & 1) << 3)) * 2;

    const __nv_bfloat16* srcs[4] = {Ahg, Alg, Bhg, Blg};
    const int tb[4] = {mBase, mBase, nBase, nBase};

    {
        char* base = smg;
#pragma unroll
        for (int ti = 0; ti < 4; ti++)
#pragma unroll
            for (int rr = 0; rr < 2; rr++) {
                int r = row0 + rr * 64;
                uint32_t dst = smem_u32(base + ti * TILE_B + (r * ASTRIDE + chunk * 8) * 2);
                cp16(dst, srcs[ti] + (size_t)(tb[ti] + r) * KDIM + chunk * 8);
            }
        asm volatile("cp.async.commit_group;");
    }

    for (int s = 0; s < NST; s++) {
        if (s + 1 < NST) {
            char* base = smg + ((s + 1) & 1) * STAGE_B;
            int k0 = (s + 1) * BKG;
#pragma unroll
            for (int ti = 0; ti < 4; ti++)
#pragma unroll
                for (int rr = 0; rr < 2; rr++) {
                    int r = row0 + rr * 64;
                    uint32_t dst = smem_u32(base + ti * TILE_B + (r * ASTRIDE + chunk * 8) * 2);
                    cp16(dst, srcs[ti] + (size_t)(tb[ti] + r) * KDIM + k0 + chunk * 8);
                }
            asm volatile("cp.async.commit_group;");
            asm volatile("cp.async.wait_group 1;");
        } else {
            asm volatile("cp.async.wait_group 0;");
        }
        __syncthreads();

        uint32_t bAh = smem_u32(smg + (s & 1) * STAGE_B);
        uint32_t bAl = bAh + TILE_B;
        uint32_t bBh = bAh + 2 * TILE_B;
        uint32_t bBl = bAh + 3 * TILE_B;

#pragma unroll
        for (int ks = 0; ks < 2; ks++) {
            const int kk2 = ks * 32;
            uint32_t ah[2][4], al[2][4];
            ldsm4(ah[0], bAh + loffA0 + kk2);
            ldsm4(ah[1], bAh + loffA1 + kk2);
            ldsm4(al[0], bAl + loffA0 + kk2);
            ldsm4(al[1], bAl + loffA1 + kk2);
#pragma unroll
            for (int p = 0; p < 4; p++) {
                uint32_t bh4[4], bl4[4];
                ldsm4(bh4, bBh + loffB + p * (16 * ASTRIDE * 2) + kk2);
                ldsm4(bl4, bBl + loffB + p * (16 * ASTRIDE * 2) + kk2);
#pragma unroll
                for (int mf = 0; mf < 2; mf++) {
                    mma16816(acc[mf][2 * p],     ah[mf], bh4[0], bh4[1]);
                    mma16816(acc[mf][2 * p],     ah[mf], bl4[0], bl4[1]);
                    mma16816(acc[mf][2 * p],     al[mf], bh4[0], bh4[1]);
                    mma16816(acc[mf][2 * p + 1], ah[mf], bh4[2], bh4[3]);
                    mma16816(acc[mf][2 * p + 1], ah[mf], bl4[2], bl4[3]);
                    mma16816(acc[mf][2 * p + 1], al[mf], bh4[2], bh4[3]);
                }
            }
        }
        __syncthreads();
    }

    if (Ch) {
#pragma unroll
        for (int mf = 0; mf < 2; mf++) {
            int row = mBase + wm * 32 + mf * 16 + g;
#pragma unroll
            for (int nf = 0; nf < 8; nf++) {
                int col = nBase + wn * 64 + nf * 8 + 2 * tq;
                float a0 = acc[mf][nf][0], a1 = acc[mf][nf][1];
                float a2 = acc[mf][nf][2], a3 = acc[mf][nf][3];
                __nv_bfloat16 h0 = __float2bfloat16(a0), h1 = __float2bfloat16(a1);
                __nv_bfloat16 h2 = __float2bfloat16(a2), h3 = __float2bfloat16(a3);
                *(uint32_t*)(Ch + (size_t)row * N + col) =
                    (uint32_t)__bfloat16_as_ushort(h0) | ((uint32_t)__bfloat16_as_ushort(h1) << 16);
                *(uint32_t*)(Ch + (size_t)(row + 8) * N + col) =
                    (uint32_t)__bfloat16_as_ushort(h2) | ((uint32_t)__bfloat16_as_ushort(h3) << 16);
                *(uint32_t*)(Cl + (size_t)row * N + col) =
                    pack_bf2(a0 - __bfloat162float(h0), a1 - __bfloat162float(h1));
                *(uint32_t*)(Cl + (size_t)(row + 8) * N + col) =
                    pack_bf2(a2 - __bfloat162float(h2), a3 - __bfloat162float(h3));
            }
        }
    } else {
#pragma unroll
        for (int mf = 0; mf < 2; mf++) {
            int row = mBase + wm * 32 + mf * 16 + g;
#pragma unroll
            for (int nf = 0; nf < 8; nf++) {
                int col = nBase + wn * 64 + nf * 8 + 2 * tq;
                *(float2*)(C + (size_t)row * N + col) =
                    make_float2(acc[mf][nf][0], acc[mf][nf][1]);
                *(float2*)(C + (size_t)(row + 8) * N + col) =
                    make_float2(acc[mf][nf][2], acc[mf][nf][3]);
            }
        }
    }
}

__global__ __launch_bounds__(256, 2) void gemm_qkv(const __nv_bfloat16* __restrict__ xh,
                                                   const __nv_bfloat16* __restrict__ xl,
                                                   const __nv_bfloat16* __restrict__ wqh,
                                                   const __nv_bfloat16* __restrict__ wql,
                                                   const __nv_bfloat16* __restrict__ wkh,
                                                   const __nv_bfloat16* __restrict__ wkl,
                                                   const __nv_bfloat16* __restrict__ wvh,
                                                   const __nv_bfloat16* __restrict__ wvl,
                                                   float* __restrict__ Q,
                                                   float* __restrict__ K,
                                                   __nv_bfloat16* __restrict__ Vh,
                                                   __nv_bfloat16* __restrict__ Vl) {
    extern __shared__ char smg[];
    int bx = blockIdx.x;
    int mBase = blockIdx.y * BM;
    if (bx < 16) {
        gemm_body(xh, xl, wqh, wql, Q, nullptr, nullptr, NQD, mBase, bx * BN, smg);
    } else if (bx < 20) {
        gemm_body(xh, xl, wkh, wkl, K, nullptr, nullptr, NKD, mBase, (bx - 16) * BN, smg);
    } else {
        gemm_body(xh, xl, wvh, wvl, nullptr, Vh, Vl, NKD, mBase, (bx - 20) * BN, smg);
    }
}

__global__ __launch_bounds__(256, 2) void gemm_plain(const __nv_bfloat16* __restrict__ Ah,
                                                     const __nv_bfloat16* __restrict__ Al,
                                                     const __nv_bfloat16* __restrict__ Bh,
                                                     const __nv_bfloat16* __restrict__ Bl,
                                                     float* __restrict__ C, int N) {
    extern __shared__ char smg[];
    gemm_body(Ah, Al, Bh, Bl, C, nullptr, nullptr, N, blockIdx.y * BM, blockIdx.x * BN, smg);
}

// ---------------------------------------------------------------------------
// RoPE: one thread per (s, j). Q outputs PRE-SCALED by 1/sqrt(HD).
// ---------------------------------------------------------------------------
__global__ void ropeQK_kernel(const float* __restrict__ Q, const float* __restrict__ K,
                              __nv_bfloat16* __restrict__ Qh, __nv_bfloat16* __restrict__ Ql,
                              __nv_bfloat16* __restrict__ Kh, __nv_bfloat16* __restrict__ Kl) {
    int idx = blockIdx.x * blockDim.x + threadIdx.x;
    if (idx >= S_LEN * 64) return;
    int j = idx & 63;
    int s = idx >> 6;
    const float sc = 0.08838834764831845f;

    float invf = expf(-logf(10000.0f) * (float)(2 * j) / (float)HD);
    float ang = (float)s * invf;
    float c, sn;
    sincosf(ang, &sn, &c);

#pragma unroll 4
    for (int hh = 0; hh < NH; hh++) {
        size_t base = (size_t)s * NQD + hh * HD;
        float a = Q[base + j], b = Q[base + j + 64];
        float ra = (a * c - b * sn) * sc;
        float rb = (b * c + a * sn) * sc;
        __nv_bfloat16 rah = __float2bfloat16(ra);
        __nv_bfloat16 rbh = __float2bfloat16(rb);
        Qh[base + j]      = rah;
        Qh[base + j + 64] = rbh;
        Ql[base + j]      = __float2bfloat16(ra - __bfloat162float(rah));
        Ql[base + j + 64] = __float2bfloat16(rb - __bfloat162float(rbh));
    }
#pragma unroll
    for (int hh = 0; hh < NKV; hh++) {
        size_t base = (size_t)s * NKD + hh * HD;
        float a = K[base + j], b = K[base + j + 64];
        float ra = a * c - b * sn;
        float rb = b * c + a * sn;
        __nv_bfloat16 rah = __float2bfloat16(ra);
        __nv_bfloat16 rbh = __float2bfloat16(rb);
        Kh[base + j]      = rah;
        Kh[base + j + 64] = rbh;
        Kl[base + j]      = __float2bfloat16(ra - __bfloat162float(rah));
        Kl[base + j + 64] = __float2bfloat16(rb - __bfloat162float(rbh));
    }
}

// ---------------------------------------------------------------------------
// HMMA flash attention (occ 1): Q fragments register-resident; 16-key chunks;
// mask-skip on interior chunks; 3-term S; 3-term PV (Ph*Vh + Pl*Vh + Ph*Vl);
// rescale-skip; heavy tiles first.
// ---------------------------------------------------------------------------
#define FQ 128
#define FCH 16
#define FSTR 136
#define FROWB (FSTR * 2)                 // 272
#define QT_B (FQ * FROWB)                // 34816
#define CH_TILE (FCH * FROWB)            // 4352
#define FCH_B (4 * CH_TILE)              // 17408
#define FSTAGE0 (2 * QT_B)               // 69632
#define FLASH_SMEM (FSTAGE0 + 2 * FCH_B) // 104448

__device__ __forceinline__ void flash_load_chunk(const __nv_bfloat16* __restrict__ Kh,
                                                 const __nv_bfloat16* __restrict__ Kl,
                                                 const __nv_bfloat16* __restrict__ Vh,
                                                 const __nv_bfloat16* __restrict__ Vl,
                                                 int k0, int kvh, char* base, int tid) {
    int r = tid >> 4, c = tid & 15;
#pragma unroll
    for (int ti = 0; ti < 4; ti++) {
        const __nv_bfloat16* s0 = (ti == 0) ? Kh : (ti == 1) ? Kl : (ti == 2) ? Vh : Vl;
        uint32_t dst = smem_u32(base + ti * CH_TILE + r * FROWB + c * 16);
        cp16(dst, s0 + (size_t)(k0 + r) * NKD + kvh * HD + c * 8);
    }
}

__global__ __launch_bounds__(256, 1) void flash_hmma(
        const __nv_bfloat16* __restrict__ Qh, const __nv_bfloat16* __restrict__ Ql,
        const __nv_bfloat16* __restrict__ Kh, const __nv_bfloat16* __restrict__ Kl,
        const __nv_bfloat16* __restrict__ Vh, const __nv_bfloat16* __restrict__ Vl,
        __nv_bfloat16* __restrict__ Oh, __nv_bfloat16* __restrict__ Ol) {
    extern __shared__ char sm[];
    const int tid = threadIdx.x;
    const int wid = tid >> 5, lane = tid & 31;
    const int g = lane >> 2, tq = lane & 3;
    const int qt = gridDim.x - 1 - blockIdx.x;   // heavy tiles first
    const int h = blockIdx.y;
    const int kvh = h >> 2;
    const int q0 = qt * FQ;
    const int rw = wid * 16;

    const int sub16 = lane & 15;
    const int hi8 = (lane >> 4) << 3;
    const int q2 = lane >> 3, sub8 = lane & 7;
    const int loffQ = ((rw + sub16) * FSTR + hi8) * 2;
    const int loffK = ((((q2 >> 1) << 3) + sub8) * FSTR + ((q2 & 1) << 3)) * 2;

    const int rmin = q0 + rw;
    const int rmax = rmin + 15;

    // ---- Q load into smem (group A) ----
#pragma unroll
    for (int ti = 0; ti < 2; ti++) {
        const __nv_bfloat16* src0 = (ti == 0) ? Qh : Ql;
#pragma unroll
        for (int ii = 0; ii < 8; ii++) {
            int rem = tid + ii * 256;
            int r = rem >> 4, c = rem & 15;
            uint32_t dst = smem_u32(sm + ti * QT_B + r * FROWB + c * 16);
            cp16(dst, src0 + (size_t)(q0 + r) * NQD + h * HD + c * 8);
        }
    }
    asm volatile("cp.async.commit_group;");

    int lo_key = q0 - (WIN - 1);
    if (lo_key < 0) lo_key = 0;
    const int kc_begin = lo_key >> 4;
    const int kc_end = (q0 + FQ - 1) >> 4;

    // ---- first KV chunk (group B) ----
    flash_load_chunk(Kh, Kl, Vh, Vl, kc_begin * FCH, kvh, sm + FSTAGE0, tid);
    asm volatile("cp.async.commit_group;");

    // ---- wait for Q (group A), load Q fragments into registers ----
    asm volatile("cp.async.wait_group 1;");
    __syncthreads();
    uint32_t qh[8][4], ql[8][4];
    {
        uint32_t bQh = smem_u32(sm);
        uint32_t bQl = bQh + QT_B;
#pragma unroll
        for (int ks = 0; ks < 8; ks++) {
            ldsm4(qh[ks], bQh + loffQ + ks * 32);
            ldsm4(ql[ks], bQl + loffQ + ks * 32);
        }
    }

    float oacc[16][4] = {};
    float m0 = -1e30f, m1 = -1e30f, l0 = 0.0f, l1 = 0.0f;

    for (int kc = kc_begin; kc <= kc_end; kc++) {
        const int buf = (kc - kc_begin) & 1;
        if (kc < kc_end) {
            flash_load_chunk(Kh, Kl, Vh, Vl, (kc + 1) * FCH, kvh,
                             sm + FSTAGE0 + (buf ^ 1) * FCH_B, tid);
            asm volatile("cp.async.commit_group;");
            asm volatile("cp.async.wait_group 1;");
        } else {
            asm volatile("cp.async.wait_group 0;");
        }
        __syncthreads();

        const int k0 = kc * FCH;
        const bool act = (k0 + FCH - 1 >= rmin - (WIN - 1)) && (k0 <= rmax);

        if (act) {
            uint32_t bKh = smem_u32(sm + FSTAGE0 + buf * FCH_B);
            uint32_t bKl = bKh + CH_TILE;
            uint32_t bVh = bKh + 2 * CH_TILE;
            uint32_t bVl = bKh + 3 * CH_TILE;

            // ---- S = Q K^T (Q frags in registers, 3-term) ----
            float sacc[2][4] = {};
#pragma unroll
            for (int ks = 0; ks < 8; ks++) {
                uint32_t kh4[4], kl4[4];
                ldsm4(kh4, bKh + loffK + ks * 32);
                ldsm4(kl4, bKl + loffK + ks * 32);
                mma16816(sacc[0], qh[ks], kh4[0], kh4[1]);
                mma16816(sacc[0], qh[ks], kl4[0], kl4[1]);
                mma16816(sacc[0], ql[ks], kh4[0], kh4[1]);
                mma16816(sacc[1], qh[ks], kh4[2], kh4[3]);
                mma16816(sacc[1], qh[ks], kl4[2], kl4[3]);
                mma16816(sacc[1], ql[ks], kh4[2], kh4[3]);
            }

            // ---- mask only boundary chunks (scale folded into Q) ----
            const int row0 = q0 + rw + g, row1 = row0 + 8;
            const bool full = (k0 >= rmax - (WIN - 1)) && (k0 + FCH - 1 <= rmin);
            if (!full) {
#pragma unroll
                for (int nf = 0; nf < 2; nf++) {
                    int colb = k0 + nf * 8 + 2 * tq;
#pragma unroll
                    for (int c = 0; c < 4; c++) {
                        int col = colb + (c & 1);
                        int row = (c < 2) ? row0 : row1;
                        bool ok = (col <= row) && (row - col < WIN);
                        if (!ok) sacc[nf][c] = -1e9f;
                    }
                }
            }

            // ---- online softmax ----
            float mx0 = fmaxf(fmaxf(sacc[0][0], sacc[0][1]), fmaxf(sacc[1][0], sacc[1][1]));
            float mx1 = fmaxf(fmaxf(sacc[0][2], sacc[0][3]), fmaxf(sacc[1][2], sacc[1][3]));
            mx0 = fmaxf(mx0, __shfl_xor_sync(0xffffffffu, mx0, 1));
            mx0 = fmaxf(mx0, __shfl_xor_sync(0xffffffffu, mx0, 2));
            mx1 = fmaxf(mx1, __shfl_xor_sync(0xffffffffu, mx1, 1));
            mx1 = fmaxf(mx1, __shfl_xor_sync(0xffffffffu, mx1, 2));
            bool upd = (mx0 > m0) || (mx1 > m1);
            float mn0 = fmaxf(m0, mx0), mn1 = fmaxf(m1, mx1);
            float al0 = __expf(m0 - mn0), al1 = __expf(m1 - mn1);
            m0 = mn0; m1 = mn1;

            float sum0 = 0.0f, sum1 = 0.0f;
#pragma unroll
            for (int nf = 0; nf < 2; nf++) {
                sacc[nf][0] = __expf(sacc[nf][0] - mn0);
                sacc[nf][1] = __expf(sacc[nf][1] - mn0);
                sacc[nf][2] = __expf(sacc[nf][2] - mn1);
                sacc[nf][3] = __expf(sacc[nf][3] - mn1);
                sum0 += sacc[nf][0] + sacc[nf][1];
                sum1 += sacc[nf][2] + sacc[nf][3];
            }
            sum0 += __shfl_xor_sync(0xffffffffu, sum0, 1);
            sum0 += __shfl_xor_sync(0xffffffffu, sum0, 2);
            sum1 += __shfl_xor_sync(0xffffffffu, sum1, 1);
            sum1 += __shfl_xor_sync(0xffffffffu, sum1, 2);
            l0 = l0 * al0 + sum0;
            l1 = l1 * al1 + sum1;

            if (__any_sync(0xffffffffu, upd)) {
#pragma unroll
                for (int on = 0; on < 16; on++) {
                    oacc[on][0] *= al0; oacc[on][1] *= al0;
                    oacc[on][2] *= al1; oacc[on][3] *= al1;
                }
            }

            // ---- pack P (bf16 hi/lo) ----
            uint32_t pah[4], pal[4];
#pragma unroll
            for (int q = 0; q < 4; q++) {
                int nf = q >> 1;
                float x = sacc[nf][(q & 1) * 2 + 0];
                float y = sacc[nf][(q & 1) * 2 + 1];
                __nv_bfloat16 hx = __float2bfloat16(x);
                __nv_bfloat16 hy = __float2bfloat16(y);
                pah[q] = (uint32_t)__bfloat16_as_ushort(hx) |
                         ((uint32_t)__bfloat16_as_ushort(hy) << 16);
                pal[q] = pack_bf2(x - __bfloat162float(hx),
                                  y - __bfloat162float(hy));
            }

            // ---- O += P V (3-term: Ph*Vh + Pl*Vh + Ph*Vl) ----
            int krow = (lane & 7) + ((lane >> 3) & 1) * 8;
#pragma unroll
            for (int vb = 0; vb < 8; vb++) {
                int ncol = vb * 16 + (lane >> 4) * 8;
                uint32_t vaddr = bVh + (krow * FSTR + ncol) * 2;
                uint32_t waddr = bVl + (krow * FSTR + ncol) * 2;
                uint32_t v0, v1, v2, v3, w0, w1, w2, w3;
                ldsm4t(v0, v1, v2, v3, vaddr);
                ldsm4t(w0, w1, w2, w3, waddr);
                mma16816(oacc[2 * vb],     pah, v0, v1);
                mma16816(oacc[2 * vb],     pal, v0, v1);
                mma16816(oacc[2 * vb],     pah, w0, w1);
                mma16816(oacc[2 * vb + 1], pah, v2, v3);
                mma16816(oacc[2 * vb + 1], pal, v2, v3);
                mma16816(oacc[2 * vb + 1], pah, w2, w3);
            }
        }
        __syncthreads();
    }

    // ---- finalize: write bf16 hi/lo ----
    float inv0 = 1.0f / l0, inv1 = 1.0f / l1;
    const int row0 = q0 + rw + g, row1 = row0 + 8;
#pragma unroll
    for (int on = 0; on < 16; on++) {
        int col = h * HD + on * 8 + 2 * tq;
        float x0 = oacc[on][0] * inv0, y0 = oacc[on][1] * inv0;
        float x1 = oacc[on][2] * inv1, y1 = oacc[on][3] * inv1;
        __nv_bfloat16 hx0 = __float2bfloat16(x0), hy0 = __float2bfloat16(y0);
        __nv_bfloat16 hx1 = __float2bfloat16(x1), hy1 = __float2bfloat16(y1);
        *(uint32_t*)(Oh + (size_t)row0 * NQD + col) =
            (uint32_t)__bfloat16_as_ushort(hx0) | ((uint32_t)__bfloat16_as_ushort(hy0) << 16);
        *(uint32_t*)(Oh + (size_t)row1 * NQD + col) =
            (uint32_t)__bfloat16_as_ushort(hx1) | ((uint32_t)__bfloat16_as_ushort(hy1) << 16);
        *(uint32_t*)(Ol + (size_t)row0 * NQD + col) =
            pack_bf2(x0 - __bfloat162float(hx0), y0 - __bfloat162float(hy0));
        *(uint32_t*)(Ol + (size_t)row1 * NQD + col) =
            pack_bf2(x1 - __bfloat162float(hx1), y1 - __bfloat162float(hy1));
    }
}

// ---------------------------------------------------------------------------
extern "C" void kernel_launch(void* const* d_in, const int* in_sizes, int n_in,
                              void* d_out, int out_size) {
    const float* x  = (const float*)d_in[0];
    // d_in[1] = attention_mask (deterministic sliding-window; computed analytically)
    const float* wq = (const float*)d_in[2];
    const float* wk = (const float*)d_in[3];
    const float* wv = (const float*)d_in[4];
    const float* wo = (const float*)d_in[5];
    float* out = (float*)d_out;

    float *Qb, *Kb;
    cudaGetSymbolAddress((void**)&Qb, g_Q);
    cudaGetSymbolAddress((void**)&Kb, g_K);
    __nv_bfloat16 *xh, *xl, *wqh, *wql, *wkh, *wkl, *wvh, *wvl, *woh, *wol, *ah, *al;
    __nv_bfloat16 *qhh, *qll, *khh, *kll, *vhh, *vll;
    cudaGetSymbolAddress((void**)&xh, g_xh);   cudaGetSymbolAddress((void**)&xl, g_xl);
    cudaGetSymbolAddress((void**)&wqh, g_wqh); cudaGetSymbolAddress((void**)&wql, g_wql);
    cudaGetSymbolAddress((void**)&wkh, g_wkh); cudaGetSymbolAddress((void**)&wkl, g_wkl);
    cudaGetSymbolAddress((void**)&wvh, g_wvh); cudaGetSymbolAddress((void**)&wvl, g_wvl);
    cudaGetSymbolAddress((void**)&woh, g_woh); cudaGetSymbolAddress((void**)&wol, g_wol);
    cudaGetSymbolAddress((void**)&ah, g_ah);   cudaGetSymbolAddress((void**)&al, g_al);
    cudaGetSymbolAddress((void**)&qhh, g_Qh);  cudaGetSymbolAddress((void**)&qll, g_Ql);
    cudaGetSymbolAddress((void**)&khh, g_Kh);  cudaGetSymbolAddress((void**)&kll, g_Kl);
    cudaGetSymbolAddress((void**)&vhh, g_Vh);  cudaGetSymbolAddress((void**)&vll, g_Vl);

    static bool attr_set = false;
    if (!attr_set) {
        cudaFuncSetAttribute(gemm_qkv, cudaFuncAttributeMaxDynamicSharedMemorySize,
                             (int)GEMM_SMEM);
        cudaFuncSetAttribute(gemm_plain, cudaFuncAttributeMaxDynamicSharedMemorySize,
                             (int)GEMM_SMEM);
        cudaFuncSetAttribute(flash_hmma, cudaFuncAttributeMaxDynamicSharedMemorySize,
                             (int)FLASH_SMEM);
        attr_set = true;
    }

    // 1. fused split of x + all weights
    splitAll_kernel<<<SPLIT_THREADS / 256, 256>>>(x, wq, wk, wv, wo,
                                                  xh, xl, wqh, wql, wkh, wkl,
                                                  wvh, wvl, woh, wol);
    // 2. fused QKV projection (V written directly as bf16 hi/lo)
    {
        dim3 gq(24, S_LEN / BM);
        gemm_qkv<<<gq, 256, GEMM_SMEM>>>(xh, xl, wqh, wql, wkh, wkl, wvh, wvl,
                                         Qb, Kb, vhh, vll);
    }
    // 3. fused RoPE Q+K -> bf16 hi/lo (Q pre-scaled by 1/sqrt(HD))
    {
        int tot = S_LEN * 64;
        ropeQK_kernel<<<(tot + 255) / 256, 256>>>(Qb, Kb, qhh, qll, khh, kll);
    }
    // 4. HMMA flash attention (Q-in-registers, 3-term PV)
    {
        dim3 g(S_LEN / FQ, NH);
        flash_hmma<<<g, 256, FLASH_SMEM>>>(qhh, qll, khh, kll, vhh, vll, ah, al);
    }
    // 5. output projection
    {
        dim3 go(HIDDIM / BN, S_LEN / BM);
        gemm_plain<<<go, 256, GEMM_SMEM>>>(ah, al, woh, wol, out, HIDDIM);
    }
}

// round 17
// speedup vs baseline: 1.0825x; 1.0825x over previous
#include <cuda_runtime.h>
#include <cuda_bf16.h>
#include <math.h>
#include <stdint.h>

#define S_LEN 2048
#define HIDDIM 2048
#define NH 16
#define NKV 4
#define HD 128
#define NQD (NH*HD)    // 2048
#define NKD (NKV*HD)   // 512
#define WIN 1024
#define KDIM 2048

// ---------------- scratch ---------------------------------------------------
__device__ float g_Q[S_LEN * NQD];
__device__ float g_K[S_LEN * NKD];

__device__ __nv_bfloat16 g_xh[S_LEN * HIDDIM], g_xl[S_LEN * HIDDIM];
__device__ __nv_bfloat16 g_wqh[NQD * HIDDIM],  g_wql[NQD * HIDDIM];
__device__ __nv_bfloat16 g_wkh[NKD * HIDDIM],  g_wkl[NKD * HIDDIM];
__device__ __nv_bfloat16 g_wvh[NKD * HIDDIM],  g_wvl[NKD * HIDDIM];
__device__ __nv_bfloat16 g_woh[HIDDIM * NQD],  g_wol[HIDDIM * NQD];
__device__ __nv_bfloat16 g_ah[S_LEN * NQD],    g_al[S_LEN * NQD];

__device__ __nv_bfloat16 g_Qh[S_LEN * NQD], g_Ql[S_LEN * NQD];
__device__ __nv_bfloat16 g_Kh[S_LEN * NKD], g_Kl[S_LEN * NKD];
__device__ __nv_bfloat16 g_Vh[S_LEN * NKD], g_Vl[S_LEN * NKD];

// ---------------- helpers ---------------------------------------------------
__device__ __forceinline__ uint32_t smem_u32(const void* p) {
    uint32_t a;
    asm("{ .reg .u64 t; cvta.to.shared.u64 t, %1; cvt.u32.u64 %0, t; }"
        : "=r"(a) : "l"(p));
    return a;
}

__device__ __forceinline__ void cp16(uint32_t dst, const void* src) {
    asm volatile("cp.async.cg.shared.global [%0], [%1], 16;" :: "r"(dst), "l"(src));
}

__device__ __forceinline__ void mma16816(float* c, const uint32_t* a,
                                         uint32_t b0, uint32_t b1) {
    asm volatile(
        "mma.sync.aligned.m16n8k16.row.col.f32.bf16.bf16.f32 "
        "{%0,%1,%2,%3}, {%4,%5,%6,%7}, {%8,%9}, {%0,%1,%2,%3};"
        : "+f"(c[0]), "+f"(c[1]), "+f"(c[2]), "+f"(c[3])
        : "r"(a[0]), "r"(a[1]), "r"(a[2]), "r"(a[3]), "r"(b0), "r"(b1));
}

__device__ __forceinline__ void ldsm4(uint32_t* r, uint32_t addr) {
    asm volatile("ldmatrix.sync.aligned.m8n8.x4.shared.b16 {%0,%1,%2,%3}, [%4];"
                 : "=r"(r[0]), "=r"(r[1]), "=r"(r[2]), "=r"(r[3]) : "r"(addr));
}

__device__ __forceinline__ void ldsm4t(uint32_t& r0, uint32_t& r1,
                                       uint32_t& r2, uint32_t& r3, uint32_t addr) {
    asm volatile("ldmatrix.sync.aligned.m8n8.x4.trans.shared.b16 {%0,%1,%2,%3}, [%4];"
                 : "=r"(r0), "=r"(r1), "=r"(r2), "=r"(r3) : "r"(addr));
}

__device__ __forceinline__ uint32_t pack_bf2(float x, float y) {
    __nv_bfloat16 hx = __float2bfloat16(x), hy = __float2bfloat16(y);
    return (uint32_t)__bfloat16_as_ushort(hx) |
           ((uint32_t)__bfloat16_as_ushort(hy) << 16);
}

// ---------------------------------------------------------------------------
// fused split: x, wq, wk, wv, wo -> bf16 hi/lo. 4 float4 per thread.
// ---------------------------------------------------------------------------
__device__ __forceinline__ void split_store(float4 v,
                                            __nv_bfloat16* __restrict__ hi,
                                            __nv_bfloat16* __restrict__ lo, int i) {
    __nv_bfloat16 h0 = __float2bfloat16(v.x);
    __nv_bfloat16 h1 = __float2bfloat16(v.y);
    __nv_bfloat16 h2 = __float2bfloat16(v.z);
    __nv_bfloat16 h3 = __float2bfloat16(v.w);
    __nv_bfloat16 l0 = __float2bfloat16(v.x - __bfloat162float(h0));
    __nv_bfloat16 l1 = __float2bfloat16(v.y - __bfloat162float(h1));
    __nv_bfloat16 l2 = __float2bfloat16(v.z - __bfloat162float(h2));
    __nv_bfloat16 l3 = __float2bfloat16(v.w - __bfloat162float(h3));
    uint2 hv, lv;
    hv.x = (uint32_t)__bfloat16_as_ushort(h0) | ((uint32_t)__bfloat16_as_ushort(h1) << 16);
    hv.y = (uint32_t)__bfloat16_as_ushort(h2) | ((uint32_t)__bfloat16_as_ushort(h3) << 16);
    lv.x = (uint32_t)__bfloat16_as_ushort(l0) | ((uint32_t)__bfloat16_as_ushort(l1) << 16);
    lv.y = (uint32_t)__bfloat16_as_ushort(l2) | ((uint32_t)__bfloat16_as_ushort(l3) << 16);
    ((uint2*)hi)[i] = hv;
    ((uint2*)lo)[i] = lv;
}

#define XQ4  262144
#define WQQ4 262144
#define WKQ4 65536
#define WVQ4 65536
#define WOQ4 262144
#define SPLIT_THREADS (XQ4 + WQQ4 + WKQ4 + WVQ4 + WOQ4)

__global__ void splitAll_kernel(const float* __restrict__ x,
                                const float* __restrict__ wq,
                                const float* __restrict__ wk,
                                const float* __restrict__ wv,
                                const float* __restrict__ wo,
                                __nv_bfloat16* xh, __nv_bfloat16* xl,
                                __nv_bfloat16* wqh, __nv_bfloat16* wql,
                                __nv_bfloat16* wkh, __nv_bfloat16* wkl,
                                __nv_bfloat16* wvh, __nv_bfloat16* wvl,
                                __nv_bfloat16* woh, __nv_bfloat16* wol) {
    int i = blockIdx.x * blockDim.x + threadIdx.x;
    const float* in; __nv_bfloat16 *hi, *lo; int base, qtr;
    if (i < XQ4)                       { in = x;  hi = xh;  lo = xl;  base = i;                      qtr = XQ4;  }
    else if (i < XQ4+WQQ4)             { in = wq; hi = wqh; lo = wql; base = i - XQ4;                qtr = WQQ4; }
    else if (i < XQ4+WQQ4+WKQ4)        { in = wk; hi = wkh; lo = wkl; base = i - XQ4-WQQ4;           qtr = WKQ4; }
    else if (i < XQ4+WQQ4+WKQ4+WVQ4)   { in = wv; hi = wvh; lo = wvl; base = i - XQ4-WQQ4-WKQ4;      qtr = WVQ4; }
    else                               { in = wo; hi = woh; lo = wol; base = i - XQ4-WQQ4-WKQ4-WVQ4; qtr = WOQ4; }
    const float4* in4 = (const float4*)in;
    float4 v0 = in4[base];
    float4 v1 = in4[base + qtr];
    float4 v2 = in4[base + 2 * qtr];
    float4 v3 = in4[base + 3 * qtr];
    split_store(v0, hi, lo, base);
    split_store(v1, hi, lo, base + qtr);
    split_store(v2, hi, lo, base + 2 * qtr);
    split_store(v3, hi, lo, base + 3 * qtr);
}

// ---------------------------------------------------------------------------
// HMMA GEMM core (proven R11 config, untouched).
// ---------------------------------------------------------------------------
#define BM 128
#define BN 128
#define BKG 32
#define ASTRIDE 40
#define TILE_B (128 * ASTRIDE * 2)
#define STAGE_B (4 * TILE_B)
#define GEMM_SMEM (2 * STAGE_B)          // 81920
#define NST (KDIM / BKG)

__device__ __forceinline__ void gemm_body(const __nv_bfloat16* __restrict__ Ahg,
                                          const __nv_bfloat16* __restrict__ Alg,
                                          const __nv_bfloat16* __restrict__ Bhg,
                                          const __nv_bfloat16* __restrict__ Blg,
                                          float* __restrict__ C,
                                          __nv_bfloat16* __restrict__ Ch,
                                          __nv_bfloat16* __restrict__ Cl,
                                          int N, int mBase, int nBase, char* smg) {
    const int t = threadIdx.x;
    const int wid = t >> 5, lane = t & 31;
    const int g = lane >> 2, tq = lane & 3;
    const int wm = wid & 3, wn = wid >> 2;

    float acc[2][8][4] = {};

    const int chunk = t & 3;
    const int row0 = t >> 2;

    const int sub16 = lane & 15;
    const int hi8 = (lane >> 4) << 3;
    const int q2 = lane >> 3, sub8 = lane & 7;
    const int loffA0 = ((wm * 32 + sub16) * ASTRIDE + hi8) * 2;
    const int loffA1 = ((wm * 32 + 16 + sub16) * ASTRIDE + hi8) * 2;
    const int loffB  = ((wn * 64 + ((q2 >> 1) << 3) + sub8) * ASTRIDE + ((q2 & 1) << 3)) * 2;

    const __nv_bfloat16* srcs[4] = {Ahg, Alg, Bhg, Blg};
    const int tb[4] = {mBase, mBase, nBase, nBase};

    {
        char* base = smg;
#pragma unroll
        for (int ti = 0; ti < 4; ti++)
#pragma unroll
            for (int rr = 0; rr < 2; rr++) {
                int r = row0 + rr * 64;
                uint32_t dst = smem_u32(base + ti * TILE_B + (r * ASTRIDE + chunk * 8) * 2);
                cp16(dst, srcs[ti] + (size_t)(tb[ti] + r) * KDIM + chunk * 8);
            }
        asm volatile("cp.async.commit_group;");
    }

    for (int s = 0; s < NST; s++) {
        if (s + 1 < NST) {
            char* base = smg + ((s + 1) & 1) * STAGE_B;
            int k0 = (s + 1) * BKG;
#pragma unroll
            for (int ti = 0; ti < 4; ti++)
#pragma unroll
                for (int rr = 0; rr < 2; rr++) {
                    int r = row0 + rr * 64;
                    uint32_t dst = smem_u32(base + ti * TILE_B + (r * ASTRIDE + chunk * 8) * 2);
                    cp16(dst, srcs[ti] + (size_t)(tb[ti] + r) * KDIM + k0 + chunk * 8);
                }
            asm volatile("cp.async.commit_group;");
            asm volatile("cp.async.wait_group 1;");
        } else {
            asm volatile("cp.async.wait_group 0;");
        }
        __syncthreads();

        uint32_t bAh = smem_u32(smg + (s & 1) * STAGE_B);
        uint32_t bAl = bAh + TILE_B;
        uint32_t bBh = bAh + 2 * TILE_B;
        uint32_t bBl = bAh + 3 * TILE_B;

#pragma unroll
        for (int ks = 0; ks < 2; ks++) {
            const int kk2 = ks * 32;
            uint32_t ah[2][4], al[2][4];
            ldsm4(ah[0], bAh + loffA0 + kk2);
            ldsm4(ah[1], bAh + loffA1 + kk2);
            ldsm4(al[0], bAl + loffA0 + kk2);
            ldsm4(al[1], bAl + loffA1 + kk2);
#pragma unroll
            for (int p = 0; p < 4; p++) {
                uint32_t bh4[4], bl4[4];
                ldsm4(bh4, bBh + loffB + p * (16 * ASTRIDE * 2) + kk2);
                ldsm4(bl4, bBl + loffB + p * (16 * ASTRIDE * 2) + kk2);
#pragma unroll
                for (int mf = 0; mf < 2; mf++) {
                    mma16816(acc[mf][2 * p],     ah[mf], bh4[0], bh4[1]);
                    mma16816(acc[mf][2 * p],     ah[mf], bl4[0], bl4[1]);
                    mma16816(acc[mf][2 * p],     al[mf], bh4[0], bh4[1]);
                    mma16816(acc[mf][2 * p + 1], ah[mf], bh4[2], bh4[3]);
                    mma16816(acc[mf][2 * p + 1], ah[mf], bl4[2], bl4[3]);
                    mma16816(acc[mf][2 * p + 1], al[mf], bh4[2], bh4[3]);
                }
            }
        }
        __syncthreads();
    }

    if (Ch) {
#pragma unroll
        for (int mf = 0; mf < 2; mf++) {
            int row = mBase + wm * 32 + mf * 16 + g;
#pragma unroll
            for (int nf = 0; nf < 8; nf++) {
                int col = nBase + wn * 64 + nf * 8 + 2 * tq;
                float a0 = acc[mf][nf][0], a1 = acc[mf][nf][1];
                float a2 = acc[mf][nf][2], a3 = acc[mf][nf][3];
                __nv_bfloat16 h0 = __float2bfloat16(a0), h1 = __float2bfloat16(a1);
                __nv_bfloat16 h2 = __float2bfloat16(a2), h3 = __float2bfloat16(a3);
                *(uint32_t*)(Ch + (size_t)row * N + col) =
                    (uint32_t)__bfloat16_as_ushort(h0) | ((uint32_t)__bfloat16_as_ushort(h1) << 16);
                *(uint32_t*)(Ch + (size_t)(row + 8) * N + col) =
                    (uint32_t)__bfloat16_as_ushort(h2) | ((uint32_t)__bfloat16_as_ushort(h3) << 16);
                *(uint32_t*)(Cl + (size_t)row * N + col) =
                    pack_bf2(a0 - __bfloat162float(h0), a1 - __bfloat162float(h1));
                *(uint32_t*)(Cl + (size_t)(row + 8) * N + col) =
                    pack_bf2(a2 - __bfloat162float(h2), a3 - __bfloat162float(h3));
            }
        }
    } else {
#pragma unroll
        for (int mf = 0; mf < 2; mf++) {
            int row = mBase + wm * 32 + mf * 16 + g;
#pragma unroll
            for (int nf = 0; nf < 8; nf++) {
                int col = nBase + wn * 64 + nf * 8 + 2 * tq;
                *(float2*)(C + (size_t)row * N + col) =
                    make_float2(acc[mf][nf][0], acc[mf][nf][1]);
                *(float2*)(C + (size_t)(row + 8) * N + col) =
                    make_float2(acc[mf][nf][2], acc[mf][nf][3]);
            }
        }
    }
}

__global__ __launch_bounds__(256, 2) void gemm_qkv(const __nv_bfloat16* __restrict__ xh,
                                                   const __nv_bfloat16* __restrict__ xl,
                                                   const __nv_bfloat16* __restrict__ wqh,
                                                   const __nv_bfloat16* __restrict__ wql,
                                                   const __nv_bfloat16* __restrict__ wkh,
                                                   const __nv_bfloat16* __restrict__ wkl,
                                                   const __nv_bfloat16* __restrict__ wvh,
                                                   const __nv_bfloat16* __restrict__ wvl,
                                                   float* __restrict__ Q,
                                                   float* __restrict__ K,
                                                   __nv_bfloat16* __restrict__ Vh,
                                                   __nv_bfloat16* __restrict__ Vl) {
    extern __shared__ char smg[];
    int bx = blockIdx.x;
    int mBase = blockIdx.y * BM;
    if (bx < 16) {
        gemm_body(xh, xl, wqh, wql, Q, nullptr, nullptr, NQD, mBase, bx * BN, smg);
    } else if (bx < 20) {
        gemm_body(xh, xl, wkh, wkl, K, nullptr, nullptr, NKD, mBase, (bx - 16) * BN, smg);
    } else {
        gemm_body(xh, xl, wvh, wvl, nullptr, Vh, Vl, NKD, mBase, (bx - 20) * BN, smg);
    }
}

__global__ __launch_bounds__(256, 2) void gemm_plain(const __nv_bfloat16* __restrict__ Ah,
                                                     const __nv_bfloat16* __restrict__ Al,
                                                     const __nv_bfloat16* __restrict__ Bh,
                                                     const __nv_bfloat16* __restrict__ Bl,
                                                     float* __restrict__ C, int N) {
    extern __shared__ char smg[];
    gemm_body(Ah, Al, Bh, Bl, C, nullptr, nullptr, N, blockIdx.y * BM, blockIdx.x * BN, smg);
}

// ---------------------------------------------------------------------------
// RoPE: one thread per (s, j). Q outputs PRE-SCALED by 1/sqrt(HD).
// ---------------------------------------------------------------------------
__global__ void ropeQK_kernel(const float* __restrict__ Q, const float* __restrict__ K,
                              __nv_bfloat16* __restrict__ Qh, __nv_bfloat16* __restrict__ Ql,
                              __nv_bfloat16* __restrict__ Kh, __nv_bfloat16* __restrict__ Kl) {
    int idx = blockIdx.x * blockDim.x + threadIdx.x;
    if (idx >= S_LEN * 64) return;
    int j = idx & 63;
    int s = idx >> 6;
    const float sc = 0.08838834764831845f;

    float invf = expf(-logf(10000.0f) * (float)(2 * j) / (float)HD);
    float ang = (float)s * invf;
    float c, sn;
    sincosf(ang, &sn, &c);

#pragma unroll 4
    for (int hh = 0; hh < NH; hh++) {
        size_t base = (size_t)s * NQD + hh * HD;
        float a = Q[base + j], b = Q[base + j + 64];
        float ra = (a * c - b * sn) * sc;
        float rb = (b * c + a * sn) * sc;
        __nv_bfloat16 rah = __float2bfloat16(ra);
        __nv_bfloat16 rbh = __float2bfloat16(rb);
        Qh[base + j]      = rah;
        Qh[base + j + 64] = rbh;
        Ql[base + j]      = __float2bfloat16(ra - __bfloat162float(rah));
        Ql[base + j + 64] = __float2bfloat16(rb - __bfloat162float(rbh));
    }
#pragma unroll
    for (int hh = 0; hh < NKV; hh++) {
        size_t base = (size_t)s * NKD + hh * HD;
        float a = K[base + j], b = K[base + j + 64];
        float ra = a * c - b * sn;
        float rb = b * c + a * sn;
        __nv_bfloat16 rah = __float2bfloat16(ra);
        __nv_bfloat16 rbh = __float2bfloat16(rb);
        Kh[base + j]      = rah;
        Kh[base + j + 64] = rbh;
        Kl[base + j]      = __float2bfloat16(ra - __bfloat162float(rah));
        Kl[base + j + 64] = __float2bfloat16(rb - __bfloat162float(rbh));
    }
}

// ---------------------------------------------------------------------------
// HMMA flash attention: FQ=64, 128 threads, 3 CTAs/SM. Q in smem; 16-key
// chunks; mask-skip interior; 3-term S + 3-term PV; rescale-skip; heavy first.
// smem = 2*17408 (Q) + 2*17408 (KV ring) = 69632 -> 3 CTAs/SM.
// ---------------------------------------------------------------------------
#define FQ 64
#define FCH 16
#define FSTR 136
#define FROWB (FSTR * 2)                 // 272
#define QT_B (FQ * FROWB)                // 17408
#define CH_TILE (FCH * FROWB)            // 4352
#define FCH_B (4 * CH_TILE)              // 17408
#define FSTAGE0 (2 * QT_B)               // 34816
#define FLASH_SMEM (FSTAGE0 + 2 * FCH_B) // 69632
#define FTH 128

__device__ __forceinline__ void flash_load_chunk(const __nv_bfloat16* __restrict__ Kh,
                                                 const __nv_bfloat16* __restrict__ Kl,
                                                 const __nv_bfloat16* __restrict__ Vh,
                                                 const __nv_bfloat16* __restrict__ Vl,
                                                 int k0, int kvh, char* base, int tid) {
    int r0 = tid >> 4, c = tid & 15;          // r0 in 0..7
#pragma unroll
    for (int ti = 0; ti < 4; ti++) {
        const __nv_bfloat16* s0 = (ti == 0) ? Kh : (ti == 1) ? Kl : (ti == 2) ? Vh : Vl;
#pragma unroll
        for (int rr = 0; rr < 2; rr++) {
            int r = r0 + rr * 8;
            uint32_t dst = smem_u32(base + ti * CH_TILE + r * FROWB + c * 16);
            cp16(dst, s0 + (size_t)(k0 + r) * NKD + kvh * HD + c * 8);
        }
    }
}

__global__ __launch_bounds__(FTH, 3) void flash_hmma(
        const __nv_bfloat16* __restrict__ Qh, const __nv_bfloat16* __restrict__ Ql,
        const __nv_bfloat16* __restrict__ Kh, const __nv_bfloat16* __restrict__ Kl,
        const __nv_bfloat16* __restrict__ Vh, const __nv_bfloat16* __restrict__ Vl,
        __nv_bfloat16* __restrict__ Oh, __nv_bfloat16* __restrict__ Ol) {
    extern __shared__ char sm[];
    const int tid = threadIdx.x;
    const int wid = tid >> 5, lane = tid & 31;
    const int g = lane >> 2, tq = lane & 3;
    const int qt = gridDim.x - 1 - blockIdx.x;   // heavy tiles first
    const int h = blockIdx.y;
    const int kvh = h >> 2;
    const int q0 = qt * FQ;
    const int rw = wid * 16;                      // warp rows within 64

    const int sub16 = lane & 15;
    const int hi8 = (lane >> 4) << 3;
    const int q2 = lane >> 3, sub8 = lane & 7;
    const int loffQ = ((rw + sub16) * FSTR + hi8) * 2;
    const int loffK = ((((q2 >> 1) << 3) + sub8) * FSTR + ((q2 & 1) << 3)) * 2;

    const int rmin = q0 + rw;
    const int rmax = rmin + 15;

    // ---- Q load (2 tiles x 64 rows x 16 col-chunks = 2048 cp16) ----
#pragma unroll
    for (int ti = 0; ti < 2; ti++) {
        const __nv_bfloat16* src0 = (ti == 0) ? Qh : Ql;
#pragma unroll
        for (int ii = 0; ii < 8; ii++) {
            int rem = tid + ii * FTH;             // 0..1023
            int r = rem >> 4, c = rem & 15;
            uint32_t dst = smem_u32(sm + ti * QT_B + r * FROWB + c * 16);
            cp16(dst, src0 + (size_t)(q0 + r) * NQD + h * HD + c * 8);
        }
    }

    int lo_key = q0 - (WIN - 1);
    if (lo_key < 0) lo_key = 0;
    const int kc_begin = lo_key >> 4;
    const int kc_end = (q0 + FQ - 1) >> 4;

    flash_load_chunk(Kh, Kl, Vh, Vl, kc_begin * FCH, kvh, sm + FSTAGE0, tid);
    asm volatile("cp.async.commit_group;");

    float oacc[16][4] = {};
    float m0 = -1e30f, m1 = -1e30f, l0 = 0.0f, l1 = 0.0f;

    for (int kc = kc_begin; kc <= kc_end; kc++) {
        const int buf = (kc - kc_begin) & 1;
        if (kc < kc_end) {
            flash_load_chunk(Kh, Kl, Vh, Vl, (kc + 1) * FCH, kvh,
                             sm + FSTAGE0 + (buf ^ 1) * FCH_B, tid);
            asm volatile("cp.async.commit_group;");
            asm volatile("cp.async.wait_group 1;");
        } else {
            asm volatile("cp.async.wait_group 0;");
        }
        __syncthreads();

        const int k0 = kc * FCH;
        const bool act = (k0 + FCH - 1 >= rmin - (WIN - 1)) && (k0 <= rmax);

        if (act) {
            uint32_t bQh = smem_u32(sm);
            uint32_t bQl = bQh + QT_B;
            uint32_t bKh = smem_u32(sm + FSTAGE0 + buf * FCH_B);
            uint32_t bKl = bKh + CH_TILE;
            uint32_t bVh = bKh + 2 * CH_TILE;
            uint32_t bVl = bKh + 3 * CH_TILE;

            // ---- S = Q K^T (3-term) ----
            float sacc[2][4] = {};
#pragma unroll
            for (int ks = 0; ks < 8; ks++) {
                const int kk2 = ks * 32;
                uint32_t qhf[4], qlf[4], kh4[4], kl4[4];
                ldsm4(qhf, bQh + loffQ + kk2);
                ldsm4(qlf, bQl + loffQ + kk2);
                ldsm4(kh4, bKh + loffK + kk2);
                ldsm4(kl4, bKl + loffK + kk2);
                mma16816(sacc[0], qhf, kh4[0], kh4[1]);
                mma16816(sacc[0], qhf, kl4[0], kl4[1]);
                mma16816(sacc[0], qlf, kh4[0], kh4[1]);
                mma16816(sacc[1], qhf, kh4[2], kh4[3]);
                mma16816(sacc[1], qhf, kl4[2], kl4[3]);
                mma16816(sacc[1], qlf, kh4[2], kh4[3]);
            }

            // ---- mask only boundary chunks (scale folded into Q) ----
            const int row0 = q0 + rw + g, row1 = row0 + 8;
            const bool full = (k0 >= rmax - (WIN - 1)) && (k0 + FCH - 1 <= rmin);
            if (!full) {
#pragma unroll
                for (int nf = 0; nf < 2; nf++) {
                    int colb = k0 + nf * 8 + 2 * tq;
#pragma unroll
                    for (int c = 0; c < 4; c++) {
                        int col = colb + (c & 1);
                        int row = (c < 2) ? row0 : row1;
                        bool ok = (col <= row) && (row - col < WIN);
                        if (!ok) sacc[nf][c] = -1e9f;
                    }
                }
            }

            // ---- online softmax ----
            float mx0 = fmaxf(fmaxf(sacc[0][0], sacc[0][1]), fmaxf(sacc[1][0], sacc[1][1]));
            float mx1 = fmaxf(fmaxf(sacc[0][2], sacc[0][3]), fmaxf(sacc[1][2], sacc[1][3]));
            mx0 = fmaxf(mx0, __shfl_xor_sync(0xffffffffu, mx0, 1));
            mx0 = fmaxf(mx0, __shfl_xor_sync(0xffffffffu, mx0, 2));
            mx1 = fmaxf(mx1, __shfl_xor_sync(0xffffffffu, mx1, 1));
            mx1 = fmaxf(mx1, __shfl_xor_sync(0xffffffffu, mx1, 2));
            bool upd = (mx0 > m0) || (mx1 > m1);
            float mn0 = fmaxf(m0, mx0), mn1 = fmaxf(m1, mx1);
            float al0 = __expf(m0 - mn0), al1 = __expf(m1 - mn1);
            m0 = mn0; m1 = mn1;

            float sum0 = 0.0f, sum1 = 0.0f;
#pragma unroll
            for (int nf = 0; nf < 2; nf++) {
                sacc[nf][0] = __expf(sacc[nf][0] - mn0);
                sacc[nf][1] = __expf(sacc[nf][1] - mn0);
                sacc[nf][2] = __expf(sacc[nf][2] - mn1);
                sacc[nf][3] = __expf(sacc[nf][3] - mn1);
                sum0 += sacc[nf][0] + sacc[nf][1];
                sum1 += sacc[nf][2] + sacc[nf][3];
            }
            sum0 += __shfl_xor_sync(0xffffffffu, sum0, 1);
            sum0 += __shfl_xor_sync(0xffffffffu, sum0, 2);
            sum1 += __shfl_xor_sync(0xffffffffu, sum1, 1);
            sum1 += __shfl_xor_sync(0xffffffffu, sum1, 2);
            l0 = l0 * al0 + sum0;
            l1 = l1 * al1 + sum1;

            if (__any_sync(0xffffffffu, upd)) {
#pragma unroll
                for (int on = 0; on < 16; on++) {
                    oacc[on][0] *= al0; oacc[on][1] *= al0;
                    oacc[on][2] *= al1; oacc[on][3] *= al1;
                }
            }

            // ---- pack P (bf16 hi/lo) ----
            uint32_t pah[4], pal[4];
#pragma unroll
            for (int q = 0; q < 4; q++) {
                int nf = q >> 1;
                float x = sacc[nf][(q & 1) * 2 + 0];
                float y = sacc[nf][(q & 1) * 2 + 1];
                __nv_bfloat16 hx = __float2bfloat16(x);
                __nv_bfloat16 hy = __float2bfloat16(y);
                pah[q] = (uint32_t)__bfloat16_as_ushort(hx) |
                         ((uint32_t)__bfloat16_as_ushort(hy) << 16);
                pal[q] = pack_bf2(x - __bfloat162float(hx),
                                  y - __bfloat162float(hy));
            }

            // ---- O += P V (3-term) ----
            int krow = (lane & 7) + ((lane >> 3) & 1) * 8;
#pragma unroll
            for (int vb = 0; vb < 8; vb++) {
                int ncol = vb * 16 + (lane >> 4) * 8;
                uint32_t vaddr = bVh + (krow * FSTR + ncol) * 2;
                uint32_t waddr = bVl + (krow * FSTR + ncol) * 2;
                uint32_t v0, v1, v2, v3, w0, w1, w2, w3;
                ldsm4t(v0, v1, v2, v3, vaddr);
                ldsm4t(w0, w1, w2, w3, waddr);
                mma16816(oacc[2 * vb],     pah, v0, v1);
                mma16816(oacc[2 * vb],     pal, v0, v1);
                mma16816(oacc[2 * vb],     pah, w0, w1);
                mma16816(oacc[2 * vb + 1], pah, v2, v3);
                mma16816(oacc[2 * vb + 1], pal, v2, v3);
                mma16816(oacc[2 * vb + 1], pah, w2, w3);
            }
        }
        __syncthreads();
    }

    // ---- finalize: write bf16 hi/lo ----
    float inv0 = 1.0f / l0, inv1 = 1.0f / l1;
    const int row0 = q0 + rw + g, row1 = row0 + 8;
#pragma unroll
    for (int on = 0; on < 16; on++) {
        int col = h * HD + on * 8 + 2 * tq;
        float x0 = oacc[on][0] * inv0, y0 = oacc[on][1] * inv0;
        float x1 = oacc[on][2] * inv1, y1 = oacc[on][3] * inv1;
        __nv_bfloat16 hx0 = __float2bfloat16(x0), hy0 = __float2bfloat16(y0);
        __nv_bfloat16 hx1 = __float2bfloat16(x1), hy1 = __float2bfloat16(y1);
        *(uint32_t*)(Oh + (size_t)row0 * NQD + col) =
            (uint32_t)__bfloat16_as_ushort(hx0) | ((uint32_t)__bfloat16_as_ushort(hy0) << 16);
        *(uint32_t*)(Oh + (size_t)row1 * NQD + col) =
            (uint32_t)__bfloat16_as_ushort(hx1) | ((uint32_t)__bfloat16_as_ushort(hy1) << 16);
        *(uint32_t*)(Ol + (size_t)row0 * NQD + col) =
            pack_bf2(x0 - __bfloat162float(hx0), y0 - __bfloat162float(hy0));
        *(uint32_t*)(Ol + (size_t)row1 * NQD + col) =
            pack_bf2(x1 - __bfloat162float(hx1), y1 - __bfloat162float(hy1));
    }
}

// ---------------------------------------------------------------------------
extern "C" void kernel_launch(void* const* d_in, const int* in_sizes, int n_in,
                              void* d_out, int out_size) {
    const float* x  = (const float*)d_in[0];
    // d_in[1] = attention_mask (deterministic sliding-window; computed analytically)
    const float* wq = (const float*)d_in[2];
    const float* wk = (const float*)d_in[3];
    const float* wv = (const float*)d_in[4];
    const float* wo = (const float*)d_in[5];
    float* out = (float*)d_out;

    float *Qb, *Kb;
    cudaGetSymbolAddress((void**)&Qb, g_Q);
    cudaGetSymbolAddress((void**)&Kb, g_K);
    __nv_bfloat16 *xh, *xl, *wqh, *wql, *wkh, *wkl, *wvh, *wvl, *woh, *wol, *ah, *al;
    __nv_bfloat16 *qhh, *qll, *khh, *kll, *vhh, *vll;
    cudaGetSymbolAddress((void**)&xh, g_xh);   cudaGetSymbolAddress((void**)&xl, g_xl);
    cudaGetSymbolAddress((void**)&wqh, g_wqh); cudaGetSymbolAddress((void**)&wql, g_wql);
    cudaGetSymbolAddress((void**)&wkh, g_wkh); cudaGetSymbolAddress((void**)&wkl, g_wkl);
    cudaGetSymbolAddress((void**)&wvh, g_wvh); cudaGetSymbolAddress((void**)&wvl, g_wvl);
    cudaGetSymbolAddress((void**)&woh, g_woh); cudaGetSymbolAddress((void**)&wol, g_wol);
    cudaGetSymbolAddress((void**)&ah, g_ah);   cudaGetSymbolAddress((void**)&al, g_al);
    cudaGetSymbolAddress((void**)&qhh, g_Qh);  cudaGetSymbolAddress((void**)&qll, g_Ql);
    cudaGetSymbolAddress((void**)&khh, g_Kh);  cudaGetSymbolAddress((void**)&kll, g_Kl);
    cudaGetSymbolAddress((void**)&vhh, g_Vh);  cudaGetSymbolAddress((void**)&vll, g_Vl);

    static bool attr_set = false;
    if (!attr_set) {
        cudaFuncSetAttribute(gemm_qkv, cudaFuncAttributeMaxDynamicSharedMemorySize,
                             (int)GEMM_SMEM);
        cudaFuncSetAttribute(gemm_plain, cudaFuncAttributeMaxDynamicSharedMemorySize,
                             (int)GEMM_SMEM);
        cudaFuncSetAttribute(flash_hmma, cudaFuncAttributeMaxDynamicSharedMemorySize,
                             (int)FLASH_SMEM);
        attr_set = true;
    }

    // 1. fused split of x + all weights
    splitAll_kernel<<<SPLIT_THREADS / 256, 256>>>(x, wq, wk, wv, wo,
                                                  xh, xl, wqh, wql, wkh, wkl,
                                                  wvh, wvl, woh, wol);
    // 2. fused QKV projection (V written directly as bf16 hi/lo)
    {
        dim3 gq(24, S_LEN / BM);
        gemm_qkv<<<gq, 256, GEMM_SMEM>>>(xh, xl, wqh, wql, wkh, wkl, wvh, wvl,
                                         Qb, Kb, vhh, vll);
    }
    // 3. fused RoPE Q+K -> bf16 hi/lo (Q pre-scaled by 1/sqrt(HD))
    {
        int tot = S_LEN * 64;
        ropeQK_kernel<<<(tot + 255) / 256, 256>>>(Qb, Kb, qhh, qll, khh, kll);
    }
    // 4. HMMA flash attention (FQ=64, 128 threads, 3 CTAs/SM)
    {
        dim3 g(S_LEN / FQ, NH);
        flash_hmma<<<g, FTH, FLASH_SMEM>>>(qhh, qll, khh, kll, vhh, vll, ah, al);
    }
    // 5. output projection
    {
        dim3 go(HIDDIM / BN, S_LEN / BM);
        gemm_plain<<<go, 256, GEMM_SMEM>>>(ah, al, woh, wol, out, HIDDIM);
    }
}